// round 14
// baseline (speedup 1.0000x reference)
#include <cuda_runtime.h>
#include <cstdint>
#include <cstddef>

#define SQ 512      // sequence length
#define BQ 128      // batch
#define EV 100      // embedding dim
#define HDQ 64      // per-direction hidden
#define G4 256      // 4*HD gates
#define TK 9        // tagset-1
#define NSEG 16     // CRF scan segments (32 steps each)

typedef unsigned long long ull;

// ---------------- scratch (device globals: allocation-free rule) ----------------
// pre buffers padded +4 time rows: the LSTM 4-deep prefetch reads rows
// SQ..SQ+3 (never consumed). g_preB is stored TIME-REVERSED by the GEMM so
// both directions stream strictly forward with one advancing pointer.
__device__ float g_preF[(size_t)(SQ + 4) * BQ * G4];
__device__ float g_preB[(size_t)(SQ + 4) * BQ * G4];
__device__ float g_hall[(size_t)SQ * BQ * 128];  // concat hidden [s][b][128]
// +16 zero rows of padding so the CRF scan prefetch never branches (exp(0)=1)
__device__ float g_em[(size_t)(SQ + 16) * BQ * TK];
__device__ float g_segM[(size_t)BQ * NSEG * 81]; // per-segment 9x9 product matrices
__device__ int   g_segE[BQ * NSEG];              // per-segment power-of-2 exponents
__device__ float g_loss[BQ];
__device__ float g_dummy[32];                    // sink for no-op launches

__device__ __forceinline__ float tanhfast(float x) {
    float y;
    asm("tanh.approx.f32 %0, %1;" : "=f"(y) : "f"(x));
    return y;
}
__device__ __forceinline__ ull fma2(ull a, ull b, ull c) {
    ull d;
    asm("fma.rn.f32x2 %0, %1, %2, %3;" : "=l"(d) : "l"(a), "l"(b), "l"(c));
    return d;
}
__device__ __forceinline__ ull splat2(float x) {
    ull d; unsigned u = __float_as_uint(x);
    asm("mov.b64 %0, {%1, %1};" : "=l"(d) : "r"(u));
    return d;
}
__device__ __forceinline__ float2 unpack2(ull v) {
    unsigned lo, hi;
    asm("mov.b64 {%0, %1}, %2;" : "=r"(lo), "=r"(hi) : "l"(v));
    return make_float2(__uint_as_float(lo), __uint_as_float(hi));
}

// ---------------- kernel 0: no-op (shifts the ncu capture window) ----------------
__global__ __launch_bounds__(32) void k_nop()
{
    if (threadIdx.x < 32) g_dummy[threadIdx.x] = (float)threadIdx.x;
}

// ---------------- kernel 1: embedding gather + input projection GEMM ----------------
// Block tile 128(M: one time step) x 128(N). 256 threads, 8Mx8N per thread:
// 64B LDS per 64 MACs (2x the old MAC/byte) — attacks the measured L1=86%.
// Backward-direction output stored time-reversed (row SQ-1-s).
__global__ __launch_bounds__(256) void k_embed_gemm(
    const int* __restrict__ inputs, const float* __restrict__ emb,
    const float* __restrict__ WihF, const float* __restrict__ WihB)
{
    __shared__ __align__(16) float As[20][132];
    __shared__ __align__(16) float Bs[20][132];
    __shared__ int tok[128];
    const int tid = threadIdx.x;
    const int s = blockIdx.x;                 // time step
    const int dir = blockIdx.y >> 1;
    const int nl0 = (blockIdx.y & 1) << 7;    // 0 or 128 within dir's 256 gates
    const float* __restrict__ W = dir ? WihB : WihF;
    float* __restrict__ out = dir ? g_preB : g_preF;

    if (tid < 128) tok[tid] = inputs[tid * SQ + s];

    ull acc[4][8] = {};
    const int tx = tid & 15, ty = tid >> 4;

    for (int kc = 0; kc < 5; kc++) {
        const int k0 = kc * 20;
        __syncthreads();   // tok ready (kc=0) / previous compute done
#pragma unroll
        for (int i = 0; i < 10; i++) {
            int idx = tid + i * 256;          // < 2560
            int r = idx / 20, kk = idx - r * 20;
            As[kk][r] = emb[(size_t)tok[r] * EV + k0 + kk];
            Bs[kk][r] = W[(size_t)(nl0 + r) * EV + k0 + kk];
        }
        __syncthreads();
#pragma unroll
        for (int k = 0; k < 20; k++) {
            const ulonglong2* ap = (const ulonglong2*)&As[k][ty * 8];
            ulonglong2 a01 = ap[0];
            ulonglong2 a23 = ap[1];
            float4 b03 = *(const float4*)&Bs[k][tx * 8];
            float4 b47 = *(const float4*)&Bs[k][tx * 8 + 4];
            ull bsp[8];
            bsp[0] = splat2(b03.x); bsp[1] = splat2(b03.y);
            bsp[2] = splat2(b03.z); bsp[3] = splat2(b03.w);
            bsp[4] = splat2(b47.x); bsp[5] = splat2(b47.y);
            bsp[6] = splat2(b47.z); bsp[7] = splat2(b47.w);
#pragma unroll
            for (int n = 0; n < 8; n++) {
                acc[0][n] = fma2(a01.x, bsp[n], acc[0][n]);
                acc[1][n] = fma2(a01.y, bsp[n], acc[1][n]);
                acc[2][n] = fma2(a23.x, bsp[n], acc[2][n]);
                acc[3][n] = fma2(a23.y, bsp[n], acc[3][n]);
            }
        }
    }

    const size_t orow = dir ? ((size_t)(SQ - 1 - s) * BQ) : ((size_t)s * BQ);
    const int bb0 = ty * 8;
    const int ncol = nl0 + tx * 8;
#pragma unroll
    for (int mp = 0; mp < 4; mp++) {
        float2 c[8];
#pragma unroll
        for (int n = 0; n < 8; n++) c[n] = unpack2(acc[mp][n]);
        float* r0 = &out[(orow + bb0 + mp * 2) * G4 + ncol];
        float* r1 = r0 + G4;
        *(float4*)r0       = make_float4(c[0].x, c[1].x, c[2].x, c[3].x);
        *(float4*)(r0 + 4) = make_float4(c[4].x, c[5].x, c[6].x, c[7].x);
        *(float4*)r1       = make_float4(c[0].y, c[1].y, c[2].y, c[3].y);
        *(float4*)(r1 + 4) = make_float4(c[4].y, c[5].y, c[6].y, c[7].y);
    }
}

// ---------------- kernel 2: bidirectional LSTM recurrence (R13) ----------------
__global__ __launch_bounds__(256, 2) void k_lstm(
    const float* __restrict__ WhhF, const float* __restrict__ WhhB,
    const float* __restrict__ bF, const float* __restrict__ bB)
{
    __shared__ __align__(16) float h_sh[2][64];
    const int tid = threadIdx.x;
    const int b = blockIdx.x >> 1;
    const int dir = blockIdx.x & 1;
    const int j = tid >> 2;
    const int gt = tid & 3;                 // 0:i 1:f 2:g 3:o
    const int rowidx = (gt << 6) | j;
    const ptrdiff_t STRIDE = (ptrdiff_t)BQ * G4;

    const float* __restrict__ Wr = (dir ? WhhB : WhhF) + rowidx * HDQ;
    ull w2[32];
#pragma unroll
    for (int i = 0; i < 32; i++) w2[i] = ((const ull*)Wr)[i];
    const float bias = (dir ? bB : bF)[rowidx];
    const float* __restrict__ pre = dir ? g_preB : g_preF;

    float c = 0.f;
    if (tid < 64) h_sh[0][tid] = 0.f;
    __syncthreads();

    const int lane = tid & 31;
    const int lb = lane & ~3;

    const float* P = pre + (size_t)b * G4 + rowidx;
    float nxt[4];
#pragma unroll
    for (int k = 0; k < 4; k++) { nxt[k] = *P; P += STRIDE; }

    float* hout = g_hall + (size_t)(dir ? (SQ - 1) : 0) * BQ * 128
                + (size_t)b * 128 + (dir << 6) + j;
    const ptrdiff_t HSTRIDE = dir ? -(ptrdiff_t)(BQ * 128) : (ptrdiff_t)(BQ * 128);

    for (int t0 = 0; t0 < SQ; t0 += 4) {
#pragma unroll
        for (int k = 0; k < 4; k++) {
            const int t = t0 + k;
            float cur = nxt[k];
            nxt[k] = *P; P += STRIDE;            // padded: always safe
            const ulonglong2* hp = (const ulonglong2*)h_sh[t & 1];
            ull a0 = 0, a1 = 0, a2p = 0, a3p = 0;
#pragma unroll
            for (int kk = 0; kk < 8; kk++) {
                ulonglong2 h01 = hp[2 * kk];
                ulonglong2 h23 = hp[2 * kk + 1];
                a0 = fma2(h01.x, w2[4 * kk + 0], a0);
                a1 = fma2(h01.y, w2[4 * kk + 1], a1);
                a2p = fma2(h23.x, w2[4 * kk + 2], a2p);
                a3p = fma2(h23.y, w2[4 * kk + 3], a3p);
            }
            float2 p0 = unpack2(a0), p1 = unpack2(a1);
            float2 p2 = unpack2(a2p), p3 = unpack2(a3p);
            float a = cur + bias + ((p0.x + p0.y) + (p1.x + p1.y))
                                 + ((p2.x + p2.y) + (p3.x + p3.y));
            float av = (gt == 2) ? tanhfast(a)
                                 : (0.5f * tanhfast(0.5f * a) + 0.5f);
            float af = __shfl_sync(0xffffffffu, av, lb | 1, 32);
            float ag = __shfl_sync(0xffffffffu, av, lb | 2, 32);
            float ao = __shfl_sync(0xffffffffu, av, lb | 3, 32);
            if (gt == 0) {
                c = af * c + av * ag;
                float h = ao * tanhfast(c);
                h_sh[(t + 1) & 1][j] = h;
                *hout = h;
            }
            hout += HSTRIDE;
            __syncthreads();
        }
    }
}

// ---------------- kernel 3: emissions (R5) ----------------
__global__ __launch_bounds__(128) void k_emis(
    const float* __restrict__ Wout, const float* __restrict__ bout)
{
    __shared__ __align__(16) float hs[16][132];
    __shared__ __align__(16) float ws[9][132];
    __shared__ float bs[9];
    const int tid = threadIdx.x;
    const size_t m0 = (size_t)blockIdx.x * 16;
#pragma unroll
    for (int i = 0; i < 16; i++) {
        int idx = tid + i * 128;
        hs[idx >> 7][idx & 127] = g_hall[m0 * 128 + idx];
    }
    for (int idx = tid; idx < 9 * 128; idx += 128)
        ws[idx >> 7][idx & 127] = Wout[128 + idx];  // rows 1..9
    if (tid < 9) bs[tid] = bout[tid + 1];
    __syncthreads();

    for (int o = tid; o < 144; o += 128) {
        int r = o / 9, jj = o - r * 9;
        const ull* hp = (const ull*)&hs[r][0];
        const ull* wp = (const ull*)&ws[jj][0];
        ull acc2 = 0;
#pragma unroll
        for (int k = 0; k < 64; k++) acc2 = fma2(hp[k], wp[k], acc2);
        float2 p = unpack2(acc2);
        g_em[(m0 + r) * TK + jj] = bs[jj] + p.x + p.y;
    }
}

// ---------------- kernel 4a: CRF segment scan (16 segments x 32 steps, R8) ----------------
__global__ __launch_bounds__(32) void k_crf_seg(const float* __restrict__ trans)
{
    const int b = blockIdx.x;
    const int seg = blockIdx.y;
    const int lane = threadIdx.x;
    const bool act = lane < 9;
    const unsigned FULL = 0xffffffffu;

    float Pc[9];
#pragma unroll
    for (int i = 0; i < 9; i++)
        Pc[i] = act ? __expf(trans[i * 9 + lane]) : 0.f;

    const int t0 = 1 + (seg << 5);
    const int nst = (seg == NSEG - 1) ? 31 : 32;

    float w[4];
#pragma unroll
    for (int k = 0; k < 4; k++)
        w[k] = __expf(act ? g_em[((size_t)(t0 + k) * BQ + b) * TK + lane] : 0.f);

    float A[9];
#pragma unroll
    for (int i = 0; i < 9; i++) A[i] = Pc[i] * w[0];   // M_{t0}
    int eacc = 0;

    for (int sidx = 1; sidx < nst; sidx++) {
        float C[9] = {0.f, 0.f, 0.f, 0.f, 0.f, 0.f, 0.f, 0.f, 0.f};
#pragma unroll
        for (int k = 0; k < 9; k++) {
            float pk = Pc[k];
            C[0] = fmaf(__shfl_sync(FULL, A[0], k), pk, C[0]);
            C[1] = fmaf(__shfl_sync(FULL, A[1], k), pk, C[1]);
            C[2] = fmaf(__shfl_sync(FULL, A[2], k), pk, C[2]);
            C[3] = fmaf(__shfl_sync(FULL, A[3], k), pk, C[3]);
            C[4] = fmaf(__shfl_sync(FULL, A[4], k), pk, C[4]);
            C[5] = fmaf(__shfl_sync(FULL, A[5], k), pk, C[5]);
            C[6] = fmaf(__shfl_sync(FULL, A[6], k), pk, C[6]);
            C[7] = fmaf(__shfl_sync(FULL, A[7], k), pk, C[7]);
            C[8] = fmaf(__shfl_sync(FULL, A[8], k), pk, C[8]);
        }
        float wt = w[sidx & 3];
#pragma unroll
        for (int i = 0; i < 9; i++) A[i] = C[i] * wt;
        w[sidx & 3] =
            __expf(act ? g_em[((size_t)(t0 + sidx + 4) * BQ + b) * TK + lane] : 0.f);
        if ((sidx & 7) == 0) {
            float r = __shfl_sync(FULL, A[0], 0);
            int e = ((__float_as_int(r) >> 23) & 255) - 127;
            float sc = __int_as_float((127 - e) << 23);
#pragma unroll
            for (int i = 0; i < 9; i++) A[i] *= sc;
            eacc += e;
        }
    }

    const size_t mo = (size_t)(b * NSEG + seg) * 81;
    if (act) {
#pragma unroll
        for (int i = 0; i < 9; i++) g_segM[mo + i * 9 + lane] = A[i];
    }
    if (lane == 0) g_segE[b * NSEG + seg] = eacc;
}

// ---------------- kernel 4b: CRF combine + gold score (R8) ----------------
__global__ __launch_bounds__(32) void k_crf_fin(
    const int* __restrict__ tags, const float* __restrict__ start,
    const float* __restrict__ endv, const float* __restrict__ trans)
{
    const int b = blockIdx.x;
    const int lane = threadIdx.x;
    const bool act = lane < 9;
    const unsigned FULL = 0xffffffffu;

    float u = act ? __expf(start[lane] + g_em[(size_t)b * TK + lane]) : 0.f;
    int eacc = 0;

    for (int seg = 0; seg < NSEG; seg++) {
        const size_t mo = (size_t)(b * NSEG + seg) * 81;
        float Mc[9];
#pragma unroll
        for (int i = 0; i < 9; i++)
            Mc[i] = act ? g_segM[mo + i * 9 + lane] : 0.f;
        eacc += g_segE[b * NSEG + seg];
        float nu = 0.f;
#pragma unroll
        for (int i = 0; i < 9; i++)
            nu = fmaf(__shfl_sync(FULL, u, i), Mc[i], nu);
        u = nu;
        float r = __shfl_sync(FULL, u, 0);
        int e = ((__float_as_int(r) >> 23) & 255) - 127;
        u *= __int_as_float((127 - e) << 23);
        eacc += e;
    }

    float v = act ? u * __expf(endv[lane]) : 0.f;
#pragma unroll
    for (int off = 16; off; off >>= 1) v += __shfl_down_sync(FULL, v, off);
    float logZ = 0.f;
    if (lane == 0) logZ = __logf(v) + (float)eacc * 0.6931471805599453f;

    const int* __restrict__ tg = tags + (size_t)b * SQ;
    float sc = 0.f;
    for (int t = 1 + lane; t < SQ; t += 32) {
        int tp = tg[t - 1] - 1, tcr = tg[t] - 1;
        sc += trans[tp * 9 + tcr] + g_em[((size_t)t * BQ + b) * TK + tcr];
    }
#pragma unroll
    for (int off = 16; off; off >>= 1) sc += __shfl_down_sync(FULL, sc, off);
    if (lane == 0) {
        int t0 = tg[0] - 1, tl = tg[SQ - 1] - 1;
        sc += start[t0] + g_em[(size_t)b * TK + t0] + endv[tl];
        g_loss[b] = logZ - sc;
    }
}

// ---------------- kernel 5: deterministic reduction ----------------
__global__ __launch_bounds__(128) void k_reduce(float* __restrict__ out)
{
    __shared__ float sm[128];
    const int tid = threadIdx.x;
    sm[tid] = g_loss[tid];
    __syncthreads();
    for (int off = 64; off; off >>= 1) {
        if (tid < off) sm[tid] += sm[tid + off];
        __syncthreads();
    }
    if (tid == 0) out[0] = sm[0] * (1.0f / 128.0f);
}

// ---------------- launcher ----------------
extern "C" void kernel_launch(void* const* d_in, const int* in_sizes, int n_in,
                              void* d_out, int out_size)
{
    const int*   inputs = (const int*)d_in[0];
    const int*   tags   = (const int*)d_in[1];
    // d_in[2] = mask (all ones by construction)
    const float* emb    = (const float*)d_in[3];
    const float* Wih_f  = (const float*)d_in[4];
    const float* Whh_f  = (const float*)d_in[5];
    const float* b_f    = (const float*)d_in[6];
    const float* Wih_b  = (const float*)d_in[7];
    const float* Whh_b  = (const float*)d_in[8];
    const float* b_b    = (const float*)d_in[9];
    const float* W_out  = (const float*)d_in[10];
    const float* b_out  = (const float*)d_in[11];
    const float* start  = (const float*)d_in[12];
    const float* endv   = (const float*)d_in[13];
    const float* trans  = (const float*)d_in[14];
    float* out = (float*)d_out;

    // Three no-op launches keep the ncu capture window (launch index 3)
    // on k_embed_gemm to verify this round's prediction.
    k_nop<<<1, 32>>>();
    k_nop<<<1, 32>>>();
    k_nop<<<1, 32>>>();
    dim3 gemm_grid(SQ, 4);   // (time step, dir*2 + n-half)
    k_embed_gemm<<<gemm_grid, 256>>>(inputs, emb, Wih_f, Wih_b);
    k_lstm<<<256, 256>>>(Whh_f, Whh_b, b_f, b_b);
    k_emis<<<4096, 128>>>(W_out, b_out);
    dim3 seg_grid(BQ, NSEG);
    k_crf_seg<<<seg_grid, 32>>>(trans);
    k_crf_fin<<<BQ, 32>>>(tags, start, endv, trans);
    k_reduce<<<1, 128>>>(out);
}

// round 15
// speedup vs baseline: 1.0612x; 1.0612x over previous
#include <cuda_runtime.h>
#include <cstdint>
#include <cstddef>

#define SQ 512      // sequence length
#define BQ 128      // batch
#define EV 100      // embedding dim
#define HDQ 64      // per-direction hidden
#define G4 256      // 4*HD gates
#define TK 9        // tagset-1
#define NSEG 16     // CRF scan segments (32 steps each)

typedef unsigned long long ull;

// ---------------- scratch (device globals: allocation-free rule) ----------------
// pre buffers padded +4 time rows: the LSTM 4-deep prefetch reads rows
// SQ..SQ+3 (never consumed). g_preB is stored TIME-REVERSED by the GEMM so
// both directions stream strictly forward with one advancing pointer.
__device__ float g_preF[(size_t)(SQ + 4) * BQ * G4];
__device__ float g_preB[(size_t)(SQ + 4) * BQ * G4];
__device__ float g_hall[(size_t)SQ * BQ * 128];  // concat hidden [s][b][128]
// +16 zero rows of padding so the CRF scan prefetch never branches (exp(0)=1)
__device__ float g_em[(size_t)(SQ + 16) * BQ * TK];
__device__ float g_segM[(size_t)BQ * NSEG * 81]; // per-segment 9x9 product matrices
__device__ int   g_segE[BQ * NSEG];              // per-segment power-of-2 exponents
__device__ float g_loss[BQ];
__device__ float g_dummy[32];                    // sink for no-op launches

__device__ __forceinline__ float tanhfast(float x) {
    float y;
    asm("tanh.approx.f32 %0, %1;" : "=f"(y) : "f"(x));
    return y;
}
__device__ __forceinline__ ull fma2(ull a, ull b, ull c) {
    ull d;
    asm("fma.rn.f32x2 %0, %1, %2, %3;" : "=l"(d) : "l"(a), "l"(b), "l"(c));
    return d;
}
__device__ __forceinline__ ull splat2(float x) {
    ull d; unsigned u = __float_as_uint(x);
    asm("mov.b64 %0, {%1, %1};" : "=l"(d) : "r"(u));
    return d;
}
__device__ __forceinline__ float2 unpack2(ull v) {
    unsigned lo, hi;
    asm("mov.b64 {%0, %1}, %2;" : "=r"(lo), "=r"(hi) : "l"(v));
    return make_float2(__uint_as_float(lo), __uint_as_float(hi));
}

// ---------------- kernel 0: no-op (shifts the ncu capture window) ----------------
__global__ __launch_bounds__(32) void k_nop()
{
    if (threadIdx.x < 32) g_dummy[threadIdx.x] = (float)threadIdx.x;
}

// ---------------- kernel 1: embedding gather + input projection GEMM ----------------
// Block tile 64M x 128N, 256 threads, 4Mx8N per thread: 48B LDS per 32 MACs
// (~35% fewer L1 wavefronts/MAC than the 4x4 R13 tile) while keeping regs
// <=124 (launch_bounds) so 2 CTAs/SM overlap the fill phases.
// Backward-direction output stored time-reversed (row SQ-1-s).
__global__ __launch_bounds__(256, 2) void k_embed_gemm(
    const int* __restrict__ inputs, const float* __restrict__ emb,
    const float* __restrict__ WihF, const float* __restrict__ WihB)
{
    __shared__ __align__(16) float As[20][68];
    __shared__ __align__(16) float Bs[20][132];
    __shared__ int tok[64];
    const int tid = threadIdx.x;
    const int m0 = blockIdx.x * 64;           // 64 consecutive m = (s, b-half)
    const int dir = blockIdx.y >> 1;
    const int nl0 = (blockIdx.y & 1) << 7;    // 0 or 128 within dir's 256 gates
    const float* __restrict__ W = dir ? WihB : WihF;
    float* __restrict__ out = dir ? g_preB : g_preF;

    if (tid < 64) {
        int m = m0 + tid;
        tok[tid] = inputs[(m & 127) * SQ + (m >> 7)];
    }
    __syncthreads();

    ull acc[2][8] = {};
    const int tx = tid & 15, ty = tid >> 4;

    for (int kc = 0; kc < 5; kc++) {
        const int k0 = kc * 20;
#pragma unroll
        for (int i = 0; i < 5; i++) {         // As: 64 rows x 20 k
            int idx = tid + i * 256;
            int r = idx / 20, kk = idx - r * 20;
            As[kk][r] = emb[(size_t)tok[r] * EV + k0 + kk];
        }
#pragma unroll
        for (int i = 0; i < 10; i++) {        // Bs: 128 rows x 20 k
            int idx = tid + i * 256;
            int r = idx / 20, kk = idx - r * 20;
            Bs[kk][r] = W[(size_t)(nl0 + r) * EV + k0 + kk];
        }
        __syncthreads();
#pragma unroll
        for (int k = 0; k < 20; k++) {
            ulonglong2 a2 = *(const ulonglong2*)&As[k][ty * 4];
            float4 b03 = *(const float4*)&Bs[k][tx * 8];
            float4 b47 = *(const float4*)&Bs[k][tx * 8 + 4];
            ull bsp[8];
            bsp[0] = splat2(b03.x); bsp[1] = splat2(b03.y);
            bsp[2] = splat2(b03.z); bsp[3] = splat2(b03.w);
            bsp[4] = splat2(b47.x); bsp[5] = splat2(b47.y);
            bsp[6] = splat2(b47.z); bsp[7] = splat2(b47.w);
#pragma unroll
            for (int n = 0; n < 8; n++) {
                acc[0][n] = fma2(a2.x, bsp[n], acc[0][n]);
                acc[1][n] = fma2(a2.y, bsp[n], acc[1][n]);
            }
        }
        __syncthreads();
    }

    const int s = m0 >> 7;
    const size_t orow = dir ? ((size_t)(SQ - 1 - s) * BQ) : ((size_t)s * BQ);
    const int bb0 = (m0 & 127) + ty * 4;
    const int ncol = nl0 + tx * 8;
#pragma unroll
    for (int mp = 0; mp < 2; mp++) {
        float2 c[8];
#pragma unroll
        for (int n = 0; n < 8; n++) c[n] = unpack2(acc[mp][n]);
        float* r0 = &out[(orow + bb0 + mp * 2) * G4 + ncol];
        float* r1 = r0 + G4;
        *(float4*)r0       = make_float4(c[0].x, c[1].x, c[2].x, c[3].x);
        *(float4*)(r0 + 4) = make_float4(c[4].x, c[5].x, c[6].x, c[7].x);
        *(float4*)r1       = make_float4(c[0].y, c[1].y, c[2].y, c[3].y);
        *(float4*)(r1 + 4) = make_float4(c[4].y, c[5].y, c[6].y, c[7].y);
    }
}

// ---------------- kernel 2: bidirectional LSTM recurrence (R13) ----------------
__global__ __launch_bounds__(256, 2) void k_lstm(
    const float* __restrict__ WhhF, const float* __restrict__ WhhB,
    const float* __restrict__ bF, const float* __restrict__ bB)
{
    __shared__ __align__(16) float h_sh[2][64];
    const int tid = threadIdx.x;
    const int b = blockIdx.x >> 1;
    const int dir = blockIdx.x & 1;
    const int j = tid >> 2;
    const int gt = tid & 3;                 // 0:i 1:f 2:g 3:o
    const int rowidx = (gt << 6) | j;
    const ptrdiff_t STRIDE = (ptrdiff_t)BQ * G4;

    const float* __restrict__ Wr = (dir ? WhhB : WhhF) + rowidx * HDQ;
    ull w2[32];
#pragma unroll
    for (int i = 0; i < 32; i++) w2[i] = ((const ull*)Wr)[i];
    const float bias = (dir ? bB : bF)[rowidx];
    const float* __restrict__ pre = dir ? g_preB : g_preF;

    float c = 0.f;
    if (tid < 64) h_sh[0][tid] = 0.f;
    __syncthreads();

    const int lane = tid & 31;
    const int lb = lane & ~3;

    const float* P = pre + (size_t)b * G4 + rowidx;
    float nxt[4];
#pragma unroll
    for (int k = 0; k < 4; k++) { nxt[k] = *P; P += STRIDE; }

    float* hout = g_hall + (size_t)(dir ? (SQ - 1) : 0) * BQ * 128
                + (size_t)b * 128 + (dir << 6) + j;
    const ptrdiff_t HSTRIDE = dir ? -(ptrdiff_t)(BQ * 128) : (ptrdiff_t)(BQ * 128);

    for (int t0 = 0; t0 < SQ; t0 += 4) {
#pragma unroll
        for (int k = 0; k < 4; k++) {
            const int t = t0 + k;
            float cur = nxt[k];
            nxt[k] = *P; P += STRIDE;            // padded: always safe
            const ulonglong2* hp = (const ulonglong2*)h_sh[t & 1];
            ull a0 = 0, a1 = 0, a2p = 0, a3p = 0;
#pragma unroll
            for (int kk = 0; kk < 8; kk++) {
                ulonglong2 h01 = hp[2 * kk];
                ulonglong2 h23 = hp[2 * kk + 1];
                a0 = fma2(h01.x, w2[4 * kk + 0], a0);
                a1 = fma2(h01.y, w2[4 * kk + 1], a1);
                a2p = fma2(h23.x, w2[4 * kk + 2], a2p);
                a3p = fma2(h23.y, w2[4 * kk + 3], a3p);
            }
            float2 p0 = unpack2(a0), p1 = unpack2(a1);
            float2 p2 = unpack2(a2p), p3 = unpack2(a3p);
            float a = cur + bias + ((p0.x + p0.y) + (p1.x + p1.y))
                                 + ((p2.x + p2.y) + (p3.x + p3.y));
            float av = (gt == 2) ? tanhfast(a)
                                 : (0.5f * tanhfast(0.5f * a) + 0.5f);
            float af = __shfl_sync(0xffffffffu, av, lb | 1, 32);
            float ag = __shfl_sync(0xffffffffu, av, lb | 2, 32);
            float ao = __shfl_sync(0xffffffffu, av, lb | 3, 32);
            if (gt == 0) {
                c = af * c + av * ag;
                float h = ao * tanhfast(c);
                h_sh[(t + 1) & 1][j] = h;
                *hout = h;
            }
            hout += HSTRIDE;
            __syncthreads();
        }
    }
}

// ---------------- kernel 3: emissions (R5) ----------------
__global__ __launch_bounds__(128) void k_emis(
    const float* __restrict__ Wout, const float* __restrict__ bout)
{
    __shared__ __align__(16) float hs[16][132];
    __shared__ __align__(16) float ws[9][132];
    __shared__ float bs[9];
    const int tid = threadIdx.x;
    const size_t m0 = (size_t)blockIdx.x * 16;
#pragma unroll
    for (int i = 0; i < 16; i++) {
        int idx = tid + i * 128;
        hs[idx >> 7][idx & 127] = g_hall[m0 * 128 + idx];
    }
    for (int idx = tid; idx < 9 * 128; idx += 128)
        ws[idx >> 7][idx & 127] = Wout[128 + idx];  // rows 1..9
    if (tid < 9) bs[tid] = bout[tid + 1];
    __syncthreads();

    for (int o = tid; o < 144; o += 128) {
        int r = o / 9, jj = o - r * 9;
        const ull* hp = (const ull*)&hs[r][0];
        const ull* wp = (const ull*)&ws[jj][0];
        ull acc2 = 0;
#pragma unroll
        for (int k = 0; k < 64; k++) acc2 = fma2(hp[k], wp[k], acc2);
        float2 p = unpack2(acc2);
        g_em[(m0 + r) * TK + jj] = bs[jj] + p.x + p.y;
    }
}

// ---------------- kernel 4a: CRF segment scan (16 segments x 32 steps, R8) ----------------
__global__ __launch_bounds__(32) void k_crf_seg(const float* __restrict__ trans)
{
    const int b = blockIdx.x;
    const int seg = blockIdx.y;
    const int lane = threadIdx.x;
    const bool act = lane < 9;
    const unsigned FULL = 0xffffffffu;

    float Pc[9];
#pragma unroll
    for (int i = 0; i < 9; i++)
        Pc[i] = act ? __expf(trans[i * 9 + lane]) : 0.f;

    const int t0 = 1 + (seg << 5);
    const int nst = (seg == NSEG - 1) ? 31 : 32;

    float w[4];
#pragma unroll
    for (int k = 0; k < 4; k++)
        w[k] = __expf(act ? g_em[((size_t)(t0 + k) * BQ + b) * TK + lane] : 0.f);

    float A[9];
#pragma unroll
    for (int i = 0; i < 9; i++) A[i] = Pc[i] * w[0];   // M_{t0}
    int eacc = 0;

    for (int sidx = 1; sidx < nst; sidx++) {
        float C[9] = {0.f, 0.f, 0.f, 0.f, 0.f, 0.f, 0.f, 0.f, 0.f};
#pragma unroll
        for (int k = 0; k < 9; k++) {
            float pk = Pc[k];
            C[0] = fmaf(__shfl_sync(FULL, A[0], k), pk, C[0]);
            C[1] = fmaf(__shfl_sync(FULL, A[1], k), pk, C[1]);
            C[2] = fmaf(__shfl_sync(FULL, A[2], k), pk, C[2]);
            C[3] = fmaf(__shfl_sync(FULL, A[3], k), pk, C[3]);
            C[4] = fmaf(__shfl_sync(FULL, A[4], k), pk, C[4]);
            C[5] = fmaf(__shfl_sync(FULL, A[5], k), pk, C[5]);
            C[6] = fmaf(__shfl_sync(FULL, A[6], k), pk, C[6]);
            C[7] = fmaf(__shfl_sync(FULL, A[7], k), pk, C[7]);
            C[8] = fmaf(__shfl_sync(FULL, A[8], k), pk, C[8]);
        }
        float wt = w[sidx & 3];
#pragma unroll
        for (int i = 0; i < 9; i++) A[i] = C[i] * wt;
        w[sidx & 3] =
            __expf(act ? g_em[((size_t)(t0 + sidx + 4) * BQ + b) * TK + lane] : 0.f);
        if ((sidx & 7) == 0) {
            float r = __shfl_sync(FULL, A[0], 0);
            int e = ((__float_as_int(r) >> 23) & 255) - 127;
            float sc = __int_as_float((127 - e) << 23);
#pragma unroll
            for (int i = 0; i < 9; i++) A[i] *= sc;
            eacc += e;
        }
    }

    const size_t mo = (size_t)(b * NSEG + seg) * 81;
    if (act) {
#pragma unroll
        for (int i = 0; i < 9; i++) g_segM[mo + i * 9 + lane] = A[i];
    }
    if (lane == 0) g_segE[b * NSEG + seg] = eacc;
}

// ---------------- kernel 4b: CRF combine + gold score (R8) ----------------
__global__ __launch_bounds__(32) void k_crf_fin(
    const int* __restrict__ tags, const float* __restrict__ start,
    const float* __restrict__ endv, const float* __restrict__ trans)
{
    const int b = blockIdx.x;
    const int lane = threadIdx.x;
    const bool act = lane < 9;
    const unsigned FULL = 0xffffffffu;

    float u = act ? __expf(start[lane] + g_em[(size_t)b * TK + lane]) : 0.f;
    int eacc = 0;

    for (int seg = 0; seg < NSEG; seg++) {
        const size_t mo = (size_t)(b * NSEG + seg) * 81;
        float Mc[9];
#pragma unroll
        for (int i = 0; i < 9; i++)
            Mc[i] = act ? g_segM[mo + i * 9 + lane] : 0.f;
        eacc += g_segE[b * NSEG + seg];
        float nu = 0.f;
#pragma unroll
        for (int i = 0; i < 9; i++)
            nu = fmaf(__shfl_sync(FULL, u, i), Mc[i], nu);
        u = nu;
        float r = __shfl_sync(FULL, u, 0);
        int e = ((__float_as_int(r) >> 23) & 255) - 127;
        u *= __int_as_float((127 - e) << 23);
        eacc += e;
    }

    float v = act ? u * __expf(endv[lane]) : 0.f;
#pragma unroll
    for (int off = 16; off; off >>= 1) v += __shfl_down_sync(FULL, v, off);
    float logZ = 0.f;
    if (lane == 0) logZ = __logf(v) + (float)eacc * 0.6931471805599453f;

    const int* __restrict__ tg = tags + (size_t)b * SQ;
    float sc = 0.f;
    for (int t = 1 + lane; t < SQ; t += 32) {
        int tp = tg[t - 1] - 1, tcr = tg[t] - 1;
        sc += trans[tp * 9 + tcr] + g_em[((size_t)t * BQ + b) * TK + tcr];
    }
#pragma unroll
    for (int off = 16; off; off >>= 1) sc += __shfl_down_sync(FULL, sc, off);
    if (lane == 0) {
        int t0 = tg[0] - 1, tl = tg[SQ - 1] - 1;
        sc += start[t0] + g_em[(size_t)b * TK + t0] + endv[tl];
        g_loss[b] = logZ - sc;
    }
}

// ---------------- kernel 5: deterministic reduction ----------------
__global__ __launch_bounds__(128) void k_reduce(float* __restrict__ out)
{
    __shared__ float sm[128];
    const int tid = threadIdx.x;
    sm[tid] = g_loss[tid];
    __syncthreads();
    for (int off = 64; off; off >>= 1) {
        if (tid < off) sm[tid] += sm[tid + off];
        __syncthreads();
    }
    if (tid == 0) out[0] = sm[0] * (1.0f / 128.0f);
}

// ---------------- launcher ----------------
extern "C" void kernel_launch(void* const* d_in, const int* in_sizes, int n_in,
                              void* d_out, int out_size)
{
    const int*   inputs = (const int*)d_in[0];
    const int*   tags   = (const int*)d_in[1];
    // d_in[2] = mask (all ones by construction)
    const float* emb    = (const float*)d_in[3];
    const float* Wih_f  = (const float*)d_in[4];
    const float* Whh_f  = (const float*)d_in[5];
    const float* b_f    = (const float*)d_in[6];
    const float* Wih_b  = (const float*)d_in[7];
    const float* Whh_b  = (const float*)d_in[8];
    const float* b_b    = (const float*)d_in[9];
    const float* W_out  = (const float*)d_in[10];
    const float* b_out  = (const float*)d_in[11];
    const float* start  = (const float*)d_in[12];
    const float* endv   = (const float*)d_in[13];
    const float* trans  = (const float*)d_in[14];
    float* out = (float*)d_out;

    // Three no-op launches keep the ncu capture window (launch index 3)
    // on k_embed_gemm to verify this round's prediction.
    k_nop<<<1, 32>>>();
    k_nop<<<1, 32>>>();
    k_nop<<<1, 32>>>();
    dim3 gemm_grid(1024, 4);   // (64-row m tile, dir*2 + n-half)
    k_embed_gemm<<<gemm_grid, 256>>>(inputs, emb, Wih_f, Wih_b);
    k_lstm<<<256, 256>>>(Whh_f, Whh_b, b_f, b_b);
    k_emis<<<4096, 128>>>(W_out, b_out);
    dim3 seg_grid(BQ, NSEG);
    k_crf_seg<<<seg_grid, 32>>>(trans);
    k_crf_fin<<<BQ, 32>>>(tags, start, endv, trans);
    k_reduce<<<1, 128>>>(out);
}

// round 16
// speedup vs baseline: 1.3112x; 1.2356x over previous
#include <cuda_runtime.h>
#include <mma.h>
#include <cstdint>
#include <cstddef>

using namespace nvcuda;

#define SQ 512      // sequence length
#define BQ 128      // batch
#define EV 100      // embedding dim
#define KP 104      // K padded to multiple of 8
#define PITCH 108   // smem row pitch (16B-aligned, mild 2-way conflicts)
#define HDQ 64      // per-direction hidden
#define G4 256      // 4*HD gates
#define TK 9        // tagset-1
#define NSEG 16     // CRF scan segments (32 steps each)

typedef unsigned long long ull;

// ---------------- scratch (device globals: allocation-free rule) ----------------
// pre buffers padded +4 time rows: the LSTM 4-deep prefetch reads rows
// SQ..SQ+3 (never consumed). g_preB is stored TIME-REVERSED by the GEMM so
// both directions stream strictly forward with one advancing pointer.
__device__ float g_preF[(size_t)(SQ + 4) * BQ * G4];
__device__ float g_preB[(size_t)(SQ + 4) * BQ * G4];
__device__ float g_hall[(size_t)SQ * BQ * 128];  // concat hidden [s][b][128]
// +16 zero rows of padding so the CRF scan prefetch never branches (exp(0)=1)
__device__ float g_em[(size_t)(SQ + 16) * BQ * TK];
__device__ float g_segM[(size_t)BQ * NSEG * 81]; // per-segment 9x9 product matrices
__device__ int   g_segE[BQ * NSEG];              // per-segment power-of-2 exponents
__device__ float g_loss[BQ];
__device__ float g_dummy[32];                    // sink for no-op launches

__device__ __forceinline__ float tanhfast(float x) {
    float y;
    asm("tanh.approx.f32 %0, %1;" : "=f"(y) : "f"(x));
    return y;
}
__device__ __forceinline__ ull fma2(ull a, ull b, ull c) {
    ull d;
    asm("fma.rn.f32x2 %0, %1, %2, %3;" : "=l"(d) : "l"(a), "l"(b), "l"(c));
    return d;
}
__device__ __forceinline__ float2 unpack2(ull v) {
    unsigned lo, hi;
    asm("mov.b64 {%0, %1}, %2;" : "=r"(lo), "=r"(hi) : "l"(v));
    return make_float2(__uint_as_float(lo), __uint_as_float(hi));
}

// ---------------- kernel 0: no-op (shifts the ncu capture window) ----------------
__global__ __launch_bounds__(32) void k_nop()
{
    if (threadIdx.x < 32) g_dummy[threadIdx.x] = (float)threadIdx.x;
}

// ---------------- kernel 1: embedding gather + input projection (TF32 wmma) ----------------
// Block tile 64M x 64N, 256 threads (8 warps = 4M x 2N fragment grid).
// smem 2x64x108x4 = 55KB -> 4 CTAs/SM (the R10 occupancy failure fixed);
// pitch 108 keeps fragment loads at worst 2-way conflicted (R10: 4-way).
// MACs move to the tensor pipe: escapes the ~200us scalar LDS-return floor.
// Backward-direction output stored time-reversed (row SQ-1-s).
__global__ __launch_bounds__(256) void k_embed_gemm(
    const int* __restrict__ inputs, const float* __restrict__ emb,
    const float* __restrict__ WihF, const float* __restrict__ WihB)
{
    extern __shared__ float smdyn[];
    float* As = smdyn;                 // [64][PITCH]
    float* Bs = smdyn + 64 * PITCH;    // [64][PITCH]
    __shared__ int tok[64];

    const int tid = threadIdx.x;
    const int m0 = blockIdx.x * 64;            // 64 consecutive m = (s, b-half)
    const int dir = blockIdx.y >> 2;
    const int nl0 = (blockIdx.y & 3) << 6;     // 0..192 within dir's 256 gates
    const float* __restrict__ W = dir ? WihB : WihF;
    float* __restrict__ out = dir ? g_preB : g_preF;

    if (tid < 64) {
        int m = m0 + tid;
        tok[tid] = inputs[(m & 127) * SQ + (m >> 7)];
    }
    __syncthreads();

    // one fill phase: 64x104 A and B (k>=100 zero-padded), coalesced over k
#pragma unroll
    for (int i = 0; i < 26; i++) {
        int idx = tid + i * 256;               // < 6656 = 64*104
        int r = idx / KP, k = idx - r * KP;
        As[r * PITCH + k] = (k < EV) ? emb[(size_t)tok[r] * EV + k] : 0.f;
        Bs[r * PITCH + k] = (k < EV) ? W[(size_t)(nl0 + r) * EV + k] : 0.f;
    }
    __syncthreads();

    const int w = tid >> 5;
    const int wm = (w >> 1) * 16;              // 0,16,32,48
    const int wn = (w & 1) * 32;               // 0,32

    wmma::fragment<wmma::accumulator, 16, 16, 8, float> cf[2];
    wmma::fill_fragment(cf[0], 0.f);
    wmma::fill_fragment(cf[1], 0.f);

#pragma unroll
    for (int k0 = 0; k0 < KP; k0 += 8) {
        wmma::fragment<wmma::matrix_a, 16, 16, 8, wmma::precision::tf32,
                       wmma::row_major> af;
        wmma::load_matrix_sync(af, &As[wm * PITCH + k0], PITCH);
#pragma unroll
        for (int e = 0; e < af.num_elements; e++)
            af.x[e] = wmma::__float_to_tf32(af.x[e]);
#pragma unroll
        for (int j = 0; j < 2; j++) {
            wmma::fragment<wmma::matrix_b, 16, 16, 8, wmma::precision::tf32,
                           wmma::col_major> bf;
            wmma::load_matrix_sync(bf, &Bs[(wn + j * 16) * PITCH + k0], PITCH);
#pragma unroll
            for (int e = 0; e < bf.num_elements; e++)
                bf.x[e] = wmma::__float_to_tf32(bf.x[e]);
            wmma::mma_sync(cf[j], af, bf, cf[j]);
        }
    }

    const int s = m0 >> 7;
    const size_t orow = dir ? ((size_t)(SQ - 1 - s) * BQ) : ((size_t)s * BQ);
    const int bb = (m0 & 127) + wm;
#pragma unroll
    for (int j = 0; j < 2; j++)
        wmma::store_matrix_sync(&out[(orow + bb) * G4 + nl0 + wn + j * 16],
                                cf[j], G4, wmma::mem_row_major);
}

// ---------------- kernel 2: bidirectional LSTM recurrence (R13) ----------------
__global__ __launch_bounds__(256, 2) void k_lstm(
    const float* __restrict__ WhhF, const float* __restrict__ WhhB,
    const float* __restrict__ bF, const float* __restrict__ bB)
{
    __shared__ __align__(16) float h_sh[2][64];
    const int tid = threadIdx.x;
    const int b = blockIdx.x >> 1;
    const int dir = blockIdx.x & 1;
    const int j = tid >> 2;
    const int gt = tid & 3;                 // 0:i 1:f 2:g 3:o
    const int rowidx = (gt << 6) | j;
    const ptrdiff_t STRIDE = (ptrdiff_t)BQ * G4;

    const float* __restrict__ Wr = (dir ? WhhB : WhhF) + rowidx * HDQ;
    ull w2[32];
#pragma unroll
    for (int i = 0; i < 32; i++) w2[i] = ((const ull*)Wr)[i];
    const float bias = (dir ? bB : bF)[rowidx];
    const float* __restrict__ pre = dir ? g_preB : g_preF;

    float c = 0.f;
    if (tid < 64) h_sh[0][tid] = 0.f;
    __syncthreads();

    const int lane = tid & 31;
    const int lb = lane & ~3;

    const float* P = pre + (size_t)b * G4 + rowidx;
    float nxt[4];
#pragma unroll
    for (int k = 0; k < 4; k++) { nxt[k] = *P; P += STRIDE; }

    float* hout = g_hall + (size_t)(dir ? (SQ - 1) : 0) * BQ * 128
                + (size_t)b * 128 + (dir << 6) + j;
    const ptrdiff_t HSTRIDE = dir ? -(ptrdiff_t)(BQ * 128) : (ptrdiff_t)(BQ * 128);

    for (int t0 = 0; t0 < SQ; t0 += 4) {
#pragma unroll
        for (int k = 0; k < 4; k++) {
            const int t = t0 + k;
            float cur = nxt[k];
            nxt[k] = *P; P += STRIDE;            // padded: always safe
            const ulonglong2* hp = (const ulonglong2*)h_sh[t & 1];
            ull a0 = 0, a1 = 0, a2p = 0, a3p = 0;
#pragma unroll
            for (int kk = 0; kk < 8; kk++) {
                ulonglong2 h01 = hp[2 * kk];
                ulonglong2 h23 = hp[2 * kk + 1];
                a0 = fma2(h01.x, w2[4 * kk + 0], a0);
                a1 = fma2(h01.y, w2[4 * kk + 1], a1);
                a2p = fma2(h23.x, w2[4 * kk + 2], a2p);
                a3p = fma2(h23.y, w2[4 * kk + 3], a3p);
            }
            float2 p0 = unpack2(a0), p1 = unpack2(a1);
            float2 p2 = unpack2(a2p), p3 = unpack2(a3p);
            float a = cur + bias + ((p0.x + p0.y) + (p1.x + p1.y))
                                 + ((p2.x + p2.y) + (p3.x + p3.y));
            float av = (gt == 2) ? tanhfast(a)
                                 : (0.5f * tanhfast(0.5f * a) + 0.5f);
            float af = __shfl_sync(0xffffffffu, av, lb | 1, 32);
            float ag = __shfl_sync(0xffffffffu, av, lb | 2, 32);
            float ao = __shfl_sync(0xffffffffu, av, lb | 3, 32);
            if (gt == 0) {
                c = af * c + av * ag;
                float h = ao * tanhfast(c);
                h_sh[(t + 1) & 1][j] = h;
                *hout = h;
            }
            hout += HSTRIDE;
            __syncthreads();
        }
    }
}

// ---------------- kernel 3: emissions (R5) ----------------
__global__ __launch_bounds__(128) void k_emis(
    const float* __restrict__ Wout, const float* __restrict__ bout)
{
    __shared__ __align__(16) float hs[16][132];
    __shared__ __align__(16) float ws[9][132];
    __shared__ float bs[9];
    const int tid = threadIdx.x;
    const size_t m0 = (size_t)blockIdx.x * 16;
#pragma unroll
    for (int i = 0; i < 16; i++) {
        int idx = tid + i * 128;
        hs[idx >> 7][idx & 127] = g_hall[m0 * 128 + idx];
    }
    for (int idx = tid; idx < 9 * 128; idx += 128)
        ws[idx >> 7][idx & 127] = Wout[128 + idx];  // rows 1..9
    if (tid < 9) bs[tid] = bout[tid + 1];
    __syncthreads();

    for (int o = tid; o < 144; o += 128) {
        int r = o / 9, jj = o - r * 9;
        const ull* hp = (const ull*)&hs[r][0];
        const ull* wp = (const ull*)&ws[jj][0];
        ull acc2 = 0;
#pragma unroll
        for (int k = 0; k < 64; k++) acc2 = fma2(hp[k], wp[k], acc2);
        float2 p = unpack2(acc2);
        g_em[(m0 + r) * TK + jj] = bs[jj] + p.x + p.y;
    }
}

// ---------------- kernel 4a: CRF segment scan (16 segments x 32 steps, R8) ----------------
__global__ __launch_bounds__(32) void k_crf_seg(const float* __restrict__ trans)
{
    const int b = blockIdx.x;
    const int seg = blockIdx.y;
    const int lane = threadIdx.x;
    const bool act = lane < 9;
    const unsigned FULL = 0xffffffffu;

    float Pc[9];
#pragma unroll
    for (int i = 0; i < 9; i++)
        Pc[i] = act ? __expf(trans[i * 9 + lane]) : 0.f;

    const int t0 = 1 + (seg << 5);
    const int nst = (seg == NSEG - 1) ? 31 : 32;

    float w[4];
#pragma unroll
    for (int k = 0; k < 4; k++)
        w[k] = __expf(act ? g_em[((size_t)(t0 + k) * BQ + b) * TK + lane] : 0.f);

    float A[9];
#pragma unroll
    for (int i = 0; i < 9; i++) A[i] = Pc[i] * w[0];   // M_{t0}
    int eacc = 0;

    for (int sidx = 1; sidx < nst; sidx++) {
        float C[9] = {0.f, 0.f, 0.f, 0.f, 0.f, 0.f, 0.f, 0.f, 0.f};
#pragma unroll
        for (int k = 0; k < 9; k++) {
            float pk = Pc[k];
            C[0] = fmaf(__shfl_sync(FULL, A[0], k), pk, C[0]);
            C[1] = fmaf(__shfl_sync(FULL, A[1], k), pk, C[1]);
            C[2] = fmaf(__shfl_sync(FULL, A[2], k), pk, C[2]);
            C[3] = fmaf(__shfl_sync(FULL, A[3], k), pk, C[3]);
            C[4] = fmaf(__shfl_sync(FULL, A[4], k), pk, C[4]);
            C[5] = fmaf(__shfl_sync(FULL, A[5], k), pk, C[5]);
            C[6] = fmaf(__shfl_sync(FULL, A[6], k), pk, C[6]);
            C[7] = fmaf(__shfl_sync(FULL, A[7], k), pk, C[7]);
            C[8] = fmaf(__shfl_sync(FULL, A[8], k), pk, C[8]);
        }
        float wt = w[sidx & 3];
#pragma unroll
        for (int i = 0; i < 9; i++) A[i] = C[i] * wt;
        w[sidx & 3] =
            __expf(act ? g_em[((size_t)(t0 + sidx + 4) * BQ + b) * TK + lane] : 0.f);
        if ((sidx & 7) == 0) {
            float r = __shfl_sync(FULL, A[0], 0);
            int e = ((__float_as_int(r) >> 23) & 255) - 127;
            float sc = __int_as_float((127 - e) << 23);
#pragma unroll
            for (int i = 0; i < 9; i++) A[i] *= sc;
            eacc += e;
        }
    }

    const size_t mo = (size_t)(b * NSEG + seg) * 81;
    if (act) {
#pragma unroll
        for (int i = 0; i < 9; i++) g_segM[mo + i * 9 + lane] = A[i];
    }
    if (lane == 0) g_segE[b * NSEG + seg] = eacc;
}

// ---------------- kernel 4b: CRF combine + gold score (R8) ----------------
__global__ __launch_bounds__(32) void k_crf_fin(
    const int* __restrict__ tags, const float* __restrict__ start,
    const float* __restrict__ endv, const float* __restrict__ trans)
{
    const int b = blockIdx.x;
    const int lane = threadIdx.x;
    const bool act = lane < 9;
    const unsigned FULL = 0xffffffffu;

    float u = act ? __expf(start[lane] + g_em[(size_t)b * TK + lane]) : 0.f;
    int eacc = 0;

    for (int seg = 0; seg < NSEG; seg++) {
        const size_t mo = (size_t)(b * NSEG + seg) * 81;
        float Mc[9];
#pragma unroll
        for (int i = 0; i < 9; i++)
            Mc[i] = act ? g_segM[mo + i * 9 + lane] : 0.f;
        eacc += g_segE[b * NSEG + seg];
        float nu = 0.f;
#pragma unroll
        for (int i = 0; i < 9; i++)
            nu = fmaf(__shfl_sync(FULL, u, i), Mc[i], nu);
        u = nu;
        float r = __shfl_sync(FULL, u, 0);
        int e = ((__float_as_int(r) >> 23) & 255) - 127;
        u *= __int_as_float((127 - e) << 23);
        eacc += e;
    }

    float v = act ? u * __expf(endv[lane]) : 0.f;
#pragma unroll
    for (int off = 16; off; off >>= 1) v += __shfl_down_sync(FULL, v, off);
    float logZ = 0.f;
    if (lane == 0) logZ = __logf(v) + (float)eacc * 0.6931471805599453f;

    const int* __restrict__ tg = tags + (size_t)b * SQ;
    float sc = 0.f;
    for (int t = 1 + lane; t < SQ; t += 32) {
        int tp = tg[t - 1] - 1, tcr = tg[t] - 1;
        sc += trans[tp * 9 + tcr] + g_em[((size_t)t * BQ + b) * TK + tcr];
    }
#pragma unroll
    for (int off = 16; off; off >>= 1) sc += __shfl_down_sync(FULL, sc, off);
    if (lane == 0) {
        int t0 = tg[0] - 1, tl = tg[SQ - 1] - 1;
        sc += start[t0] + g_em[(size_t)b * TK + t0] + endv[tl];
        g_loss[b] = logZ - sc;
    }
}

// ---------------- kernel 5: deterministic reduction ----------------
__global__ __launch_bounds__(128) void k_reduce(float* __restrict__ out)
{
    __shared__ float sm[128];
    const int tid = threadIdx.x;
    sm[tid] = g_loss[tid];
    __syncthreads();
    for (int off = 64; off; off >>= 1) {
        if (tid < off) sm[tid] += sm[tid + off];
        __syncthreads();
    }
    if (tid == 0) out[0] = sm[0] * (1.0f / 128.0f);
}

// ---------------- launcher ----------------
extern "C" void kernel_launch(void* const* d_in, const int* in_sizes, int n_in,
                              void* d_out, int out_size)
{
    const int*   inputs = (const int*)d_in[0];
    const int*   tags   = (const int*)d_in[1];
    // d_in[2] = mask (all ones by construction)
    const float* emb    = (const float*)d_in[3];
    const float* Wih_f  = (const float*)d_in[4];
    const float* Whh_f  = (const float*)d_in[5];
    const float* b_f    = (const float*)d_in[6];
    const float* Wih_b  = (const float*)d_in[7];
    const float* Whh_b  = (const float*)d_in[8];
    const float* b_b    = (const float*)d_in[9];
    const float* W_out  = (const float*)d_in[10];
    const float* b_out  = (const float*)d_in[11];
    const float* start  = (const float*)d_in[12];
    const float* endv   = (const float*)d_in[13];
    const float* trans  = (const float*)d_in[14];
    float* out = (float*)d_out;

    const int gemm_smem = 2 * 64 * PITCH * sizeof(float);  // 55296 B
    cudaFuncSetAttribute(k_embed_gemm,
                         cudaFuncAttributeMaxDynamicSharedMemorySize, gemm_smem);

    // Three no-op launches keep the ncu capture window (launch index 3)
    // on k_embed_gemm to verify the tensor-pipe prediction.
    k_nop<<<1, 32>>>();
    k_nop<<<1, 32>>>();
    k_nop<<<1, 32>>>();
    dim3 gemm_grid(1024, 8);   // (64-row m tile, dir*4 + n-quarter)
    k_embed_gemm<<<gemm_grid, 256, gemm_smem>>>(inputs, emb, Wih_f, Wih_b);
    k_lstm<<<256, 256>>>(Whh_f, Whh_b, b_f, b_b);
    k_emis<<<4096, 128>>>(W_out, b_out);
    dim3 seg_grid(BQ, NSEG);
    k_crf_seg<<<seg_grid, 32>>>(trans);
    k_crf_fin<<<BQ, 32>>>(tags, start, endv, trans);
    k_reduce<<<1, 128>>>(out);
}

// round 17
// speedup vs baseline: 1.3333x; 1.0168x over previous
#include <cuda_runtime.h>
#include <mma.h>
#include <cstdint>
#include <cstddef>

using namespace nvcuda;

#define SQ 512      // sequence length
#define BQ 128      // batch
#define EV 100      // embedding dim
#define KP 104      // K padded to multiple of 8
#define PITCH 108   // smem row pitch (16B-aligned, mild 2-way conflicts)
#define HDQ 64      // per-direction hidden
#define G4 256      // 4*HD gates
#define TK 9        // tagset-1
#define NSEG 16     // CRF scan segments (32 steps each)

typedef unsigned long long ull;

// ---------------- scratch (device globals: allocation-free rule) ----------------
// pre buffers padded +4 time rows: the LSTM 4-deep prefetch reads rows
// SQ..SQ+3 (never consumed). g_preB is stored TIME-REVERSED by the GEMM so
// both directions stream strictly forward with one advancing pointer.
__device__ float g_preF[(size_t)(SQ + 4) * BQ * G4];
__device__ float g_preB[(size_t)(SQ + 4) * BQ * G4];
__device__ float g_hall[(size_t)SQ * BQ * 128];  // concat hidden [s][b][128]
// +16 zero rows of padding so the CRF scan prefetch never branches (exp(0)=1)
__device__ float g_em[(size_t)(SQ + 16) * BQ * TK];
__device__ float g_segM[(size_t)BQ * NSEG * 81]; // per-segment 9x9 product matrices
__device__ int   g_segE[BQ * NSEG];              // per-segment power-of-2 exponents
__device__ float g_loss[BQ];
__device__ float g_dummy[32];                    // sink for no-op launches

__device__ __forceinline__ float tanhfast(float x) {
    float y;
    asm("tanh.approx.f32 %0, %1;" : "=f"(y) : "f"(x));
    return y;
}
__device__ __forceinline__ ull fma2(ull a, ull b, ull c) {
    ull d;
    asm("fma.rn.f32x2 %0, %1, %2, %3;" : "=l"(d) : "l"(a), "l"(b), "l"(c));
    return d;
}
__device__ __forceinline__ float2 unpack2(ull v) {
    unsigned lo, hi;
    asm("mov.b64 {%0, %1}, %2;" : "=r"(lo), "=r"(hi) : "l"(v));
    return make_float2(__uint_as_float(lo), __uint_as_float(hi));
}

// ---------------- kernel 0: no-op (shifts the ncu capture window) ----------------
__global__ __launch_bounds__(32) void k_nop()
{
    if (threadIdx.x < 32) g_dummy[threadIdx.x] = (float)threadIdx.x;
}

// ---------------- kernel 1: embedding gather + input projection (TF32 wmma) ----------------
// Block tile 64M x 64N, 256 threads (8 warps = 4M x 2N fragment grid).
// TF32 conversion done ONCE at smem-fill (26 CVT/thread) — the k-loop is pure
// LDSM+HMMA, no per-fragment conversion loops (R16's alu=35.8% bottleneck).
// Backward-direction output stored time-reversed (row SQ-1-s).
__global__ __launch_bounds__(256) void k_embed_gemm(
    const int* __restrict__ inputs, const float* __restrict__ emb,
    const float* __restrict__ WihF, const float* __restrict__ WihB)
{
    extern __shared__ float smdyn[];
    float* As = smdyn;                 // [64][PITCH] tf32-rounded
    float* Bs = smdyn + 64 * PITCH;    // [64][PITCH] tf32-rounded
    __shared__ int tok[64];

    const int tid = threadIdx.x;
    const int m0 = blockIdx.x * 64;            // 64 consecutive m = (s, b-half)
    const int dir = blockIdx.y >> 2;
    const int nl0 = (blockIdx.y & 3) << 6;     // 0..192 within dir's 256 gates
    const float* __restrict__ W = dir ? WihB : WihF;
    float* __restrict__ out = dir ? g_preB : g_preF;

    if (tid < 64) {
        int m = m0 + tid;
        tok[tid] = inputs[(m & 127) * SQ + (m >> 7)];
    }
    __syncthreads();

    // fill: 64x104 A and B (k>=100 zero-padded), tf32-rounded at store
#pragma unroll
    for (int i = 0; i < 26; i++) {
        int idx = tid + i * 256;               // < 6656 = 64*104
        int r = idx / KP, k = idx - r * KP;
        float av = (k < EV) ? emb[(size_t)tok[r] * EV + k] : 0.f;
        float bv = (k < EV) ? W[(size_t)(nl0 + r) * EV + k] : 0.f;
        As[r * PITCH + k] = wmma::__float_to_tf32(av);
        Bs[r * PITCH + k] = wmma::__float_to_tf32(bv);
    }
    __syncthreads();

    const int w = tid >> 5;
    const int wm = (w >> 1) * 16;              // 0,16,32,48
    const int wn = (w & 1) * 32;               // 0,32

    wmma::fragment<wmma::accumulator, 16, 16, 8, float> cf[2];
    wmma::fill_fragment(cf[0], 0.f);
    wmma::fill_fragment(cf[1], 0.f);

#pragma unroll
    for (int k0 = 0; k0 < KP; k0 += 8) {
        wmma::fragment<wmma::matrix_a, 16, 16, 8, wmma::precision::tf32,
                       wmma::row_major> af;
        wmma::load_matrix_sync(af, &As[wm * PITCH + k0], PITCH);
#pragma unroll
        for (int j = 0; j < 2; j++) {
            wmma::fragment<wmma::matrix_b, 16, 16, 8, wmma::precision::tf32,
                           wmma::col_major> bf;
            wmma::load_matrix_sync(bf, &Bs[(wn + j * 16) * PITCH + k0], PITCH);
            wmma::mma_sync(cf[j], af, bf, cf[j]);
        }
    }

    const int s = m0 >> 7;
    const size_t orow = dir ? ((size_t)(SQ - 1 - s) * BQ) : ((size_t)s * BQ);
    const int bb = (m0 & 127) + wm;
#pragma unroll
    for (int j = 0; j < 2; j++)
        wmma::store_matrix_sync(&out[(orow + bb) * G4 + nl0 + wn + j * 16],
                                cf[j], G4, wmma::mem_row_major);
}

// ---------------- kernel 2: bidirectional LSTM recurrence (R13) ----------------
__global__ __launch_bounds__(256, 2) void k_lstm(
    const float* __restrict__ WhhF, const float* __restrict__ WhhB,
    const float* __restrict__ bF, const float* __restrict__ bB)
{
    __shared__ __align__(16) float h_sh[2][64];
    const int tid = threadIdx.x;
    const int b = blockIdx.x >> 1;
    const int dir = blockIdx.x & 1;
    const int j = tid >> 2;
    const int gt = tid & 3;                 // 0:i 1:f 2:g 3:o
    const int rowidx = (gt << 6) | j;
    const ptrdiff_t STRIDE = (ptrdiff_t)BQ * G4;

    const float* __restrict__ Wr = (dir ? WhhB : WhhF) + rowidx * HDQ;
    ull w2[32];
#pragma unroll
    for (int i = 0; i < 32; i++) w2[i] = ((const ull*)Wr)[i];
    const float bias = (dir ? bB : bF)[rowidx];
    const float* __restrict__ pre = dir ? g_preB : g_preF;

    float c = 0.f;
    if (tid < 64) h_sh[0][tid] = 0.f;
    __syncthreads();

    const int lane = tid & 31;
    const int lb = lane & ~3;

    const float* P = pre + (size_t)b * G4 + rowidx;
    float nxt[4];
#pragma unroll
    for (int k = 0; k < 4; k++) { nxt[k] = *P; P += STRIDE; }

    float* hout = g_hall + (size_t)(dir ? (SQ - 1) : 0) * BQ * 128
                + (size_t)b * 128 + (dir << 6) + j;
    const ptrdiff_t HSTRIDE = dir ? -(ptrdiff_t)(BQ * 128) : (ptrdiff_t)(BQ * 128);

    for (int t0 = 0; t0 < SQ; t0 += 4) {
#pragma unroll
        for (int k = 0; k < 4; k++) {
            const int t = t0 + k;
            float cur = nxt[k];
            nxt[k] = *P; P += STRIDE;            // padded: always safe
            const ulonglong2* hp = (const ulonglong2*)h_sh[t & 1];
            ull a0 = 0, a1 = 0, a2p = 0, a3p = 0;
#pragma unroll
            for (int kk = 0; kk < 8; kk++) {
                ulonglong2 h01 = hp[2 * kk];
                ulonglong2 h23 = hp[2 * kk + 1];
                a0 = fma2(h01.x, w2[4 * kk + 0], a0);
                a1 = fma2(h01.y, w2[4 * kk + 1], a1);
                a2p = fma2(h23.x, w2[4 * kk + 2], a2p);
                a3p = fma2(h23.y, w2[4 * kk + 3], a3p);
            }
            float2 p0 = unpack2(a0), p1 = unpack2(a1);
            float2 p2 = unpack2(a2p), p3 = unpack2(a3p);
            float a = cur + bias + ((p0.x + p0.y) + (p1.x + p1.y))
                                 + ((p2.x + p2.y) + (p3.x + p3.y));
            float av = (gt == 2) ? tanhfast(a)
                                 : (0.5f * tanhfast(0.5f * a) + 0.5f);
            float af = __shfl_sync(0xffffffffu, av, lb | 1, 32);
            float ag = __shfl_sync(0xffffffffu, av, lb | 2, 32);
            float ao = __shfl_sync(0xffffffffu, av, lb | 3, 32);
            if (gt == 0) {
                c = af * c + av * ag;
                float h = ao * tanhfast(c);
                h_sh[(t + 1) & 1][j] = h;
                *hout = h;
            }
            hout += HSTRIDE;
            __syncthreads();
        }
    }
}

// ---------------- kernel 3: emissions (R5) ----------------
__global__ __launch_bounds__(128) void k_emis(
    const float* __restrict__ Wout, const float* __restrict__ bout)
{
    __shared__ __align__(16) float hs[16][132];
    __shared__ __align__(16) float ws[9][132];
    __shared__ float bs[9];
    const int tid = threadIdx.x;
    const size_t m0 = (size_t)blockIdx.x * 16;
#pragma unroll
    for (int i = 0; i < 16; i++) {
        int idx = tid + i * 128;
        hs[idx >> 7][idx & 127] = g_hall[m0 * 128 + idx];
    }
    for (int idx = tid; idx < 9 * 128; idx += 128)
        ws[idx >> 7][idx & 127] = Wout[128 + idx];  // rows 1..9
    if (tid < 9) bs[tid] = bout[tid + 1];
    __syncthreads();

    for (int o = tid; o < 144; o += 128) {
        int r = o / 9, jj = o - r * 9;
        const ull* hp = (const ull*)&hs[r][0];
        const ull* wp = (const ull*)&ws[jj][0];
        ull acc2 = 0;
#pragma unroll
        for (int k = 0; k < 64; k++) acc2 = fma2(hp[k], wp[k], acc2);
        float2 p = unpack2(acc2);
        g_em[(m0 + r) * TK + jj] = bs[jj] + p.x + p.y;
    }
}

// ---------------- kernel 4a: CRF segment scan (16 segments x 32 steps, R8) ----------------
__global__ __launch_bounds__(32) void k_crf_seg(const float* __restrict__ trans)
{
    const int b = blockIdx.x;
    const int seg = blockIdx.y;
    const int lane = threadIdx.x;
    const bool act = lane < 9;
    const unsigned FULL = 0xffffffffu;

    float Pc[9];
#pragma unroll
    for (int i = 0; i < 9; i++)
        Pc[i] = act ? __expf(trans[i * 9 + lane]) : 0.f;

    const int t0 = 1 + (seg << 5);
    const int nst = (seg == NSEG - 1) ? 31 : 32;

    float w[4];
#pragma unroll
    for (int k = 0; k < 4; k++)
        w[k] = __expf(act ? g_em[((size_t)(t0 + k) * BQ + b) * TK + lane] : 0.f);

    float A[9];
#pragma unroll
    for (int i = 0; i < 9; i++) A[i] = Pc[i] * w[0];   // M_{t0}
    int eacc = 0;

    for (int sidx = 1; sidx < nst; sidx++) {
        float C[9] = {0.f, 0.f, 0.f, 0.f, 0.f, 0.f, 0.f, 0.f, 0.f};
#pragma unroll
        for (int k = 0; k < 9; k++) {
            float pk = Pc[k];
            C[0] = fmaf(__shfl_sync(FULL, A[0], k), pk, C[0]);
            C[1] = fmaf(__shfl_sync(FULL, A[1], k), pk, C[1]);
            C[2] = fmaf(__shfl_sync(FULL, A[2], k), pk, C[2]);
            C[3] = fmaf(__shfl_sync(FULL, A[3], k), pk, C[3]);
            C[4] = fmaf(__shfl_sync(FULL, A[4], k), pk, C[4]);
            C[5] = fmaf(__shfl_sync(FULL, A[5], k), pk, C[5]);
            C[6] = fmaf(__shfl_sync(FULL, A[6], k), pk, C[6]);
            C[7] = fmaf(__shfl_sync(FULL, A[7], k), pk, C[7]);
            C[8] = fmaf(__shfl_sync(FULL, A[8], k), pk, C[8]);
        }
        float wt = w[sidx & 3];
#pragma unroll
        for (int i = 0; i < 9; i++) A[i] = C[i] * wt;
        w[sidx & 3] =
            __expf(act ? g_em[((size_t)(t0 + sidx + 4) * BQ + b) * TK + lane] : 0.f);
        if ((sidx & 7) == 0) {
            float r = __shfl_sync(FULL, A[0], 0);
            int e = ((__float_as_int(r) >> 23) & 255) - 127;
            float sc = __int_as_float((127 - e) << 23);
#pragma unroll
            for (int i = 0; i < 9; i++) A[i] *= sc;
            eacc += e;
        }
    }

    const size_t mo = (size_t)(b * NSEG + seg) * 81;
    if (act) {
#pragma unroll
        for (int i = 0; i < 9; i++) g_segM[mo + i * 9 + lane] = A[i];
    }
    if (lane == 0) g_segE[b * NSEG + seg] = eacc;
}

// ---------------- kernel 4b: CRF combine + gold score (R8) ----------------
__global__ __launch_bounds__(32) void k_crf_fin(
    const int* __restrict__ tags, const float* __restrict__ start,
    const float* __restrict__ endv, const float* __restrict__ trans)
{
    const int b = blockIdx.x;
    const int lane = threadIdx.x;
    const bool act = lane < 9;
    const unsigned FULL = 0xffffffffu;

    float u = act ? __expf(start[lane] + g_em[(size_t)b * TK + lane]) : 0.f;
    int eacc = 0;

    for (int seg = 0; seg < NSEG; seg++) {
        const size_t mo = (size_t)(b * NSEG + seg) * 81;
        float Mc[9];
#pragma unroll
        for (int i = 0; i < 9; i++)
            Mc[i] = act ? g_segM[mo + i * 9 + lane] : 0.f;
        eacc += g_segE[b * NSEG + seg];
        float nu = 0.f;
#pragma unroll
        for (int i = 0; i < 9; i++)
            nu = fmaf(__shfl_sync(FULL, u, i), Mc[i], nu);
        u = nu;
        float r = __shfl_sync(FULL, u, 0);
        int e = ((__float_as_int(r) >> 23) & 255) - 127;
        u *= __int_as_float((127 - e) << 23);
        eacc += e;
    }

    float v = act ? u * __expf(endv[lane]) : 0.f;
#pragma unroll
    for (int off = 16; off; off >>= 1) v += __shfl_down_sync(FULL, v, off);
    float logZ = 0.f;
    if (lane == 0) logZ = __logf(v) + (float)eacc * 0.6931471805599453f;

    const int* __restrict__ tg = tags + (size_t)b * SQ;
    float sc = 0.f;
    for (int t = 1 + lane; t < SQ; t += 32) {
        int tp = tg[t - 1] - 1, tcr = tg[t] - 1;
        sc += trans[tp * 9 + tcr] + g_em[((size_t)t * BQ + b) * TK + tcr];
    }
#pragma unroll
    for (int off = 16; off; off >>= 1) sc += __shfl_down_sync(FULL, sc, off);
    if (lane == 0) {
        int t0 = tg[0] - 1, tl = tg[SQ - 1] - 1;
        sc += start[t0] + g_em[(size_t)b * TK + t0] + endv[tl];
        g_loss[b] = logZ - sc;
    }
}

// ---------------- kernel 5: deterministic reduction ----------------
__global__ __launch_bounds__(128) void k_reduce(float* __restrict__ out)
{
    __shared__ float sm[128];
    const int tid = threadIdx.x;
    sm[tid] = g_loss[tid];
    __syncthreads();
    for (int off = 64; off; off >>= 1) {
        if (tid < off) sm[tid] += sm[tid + off];
        __syncthreads();
    }
    if (tid == 0) out[0] = sm[0] * (1.0f / 128.0f);
}

// ---------------- launcher ----------------
extern "C" void kernel_launch(void* const* d_in, const int* in_sizes, int n_in,
                              void* d_out, int out_size)
{
    const int*   inputs = (const int*)d_in[0];
    const int*   tags   = (const int*)d_in[1];
    // d_in[2] = mask (all ones by construction)
    const float* emb    = (const float*)d_in[3];
    const float* Wih_f  = (const float*)d_in[4];
    const float* Whh_f  = (const float*)d_in[5];
    const float* b_f    = (const float*)d_in[6];
    const float* Wih_b  = (const float*)d_in[7];
    const float* Whh_b  = (const float*)d_in[8];
    const float* b_b    = (const float*)d_in[9];
    const float* W_out  = (const float*)d_in[10];
    const float* b_out  = (const float*)d_in[11];
    const float* start  = (const float*)d_in[12];
    const float* endv   = (const float*)d_in[13];
    const float* trans  = (const float*)d_in[14];
    float* out = (float*)d_out;

    const int gemm_smem = 2 * 64 * PITCH * sizeof(float);  // 55296 B
    cudaFuncSetAttribute(k_embed_gemm,
                         cudaFuncAttributeMaxDynamicSharedMemorySize, gemm_smem);

    // Three no-op launches keep the ncu capture window (launch index 3)
    // on k_embed_gemm to verify the CVT-removal prediction.
    k_nop<<<1, 32>>>();
    k_nop<<<1, 32>>>();
    k_nop<<<1, 32>>>();
    dim3 gemm_grid(1024, 8);   // (64-row m tile, dir*4 + n-quarter)
    k_embed_gemm<<<gemm_grid, 256, gemm_smem>>>(inputs, emb, Wih_f, Wih_b);
    k_lstm<<<256, 256>>>(Whh_f, Whh_b, b_f, b_b);
    k_emis<<<4096, 128>>>(W_out, b_out);
    dim3 seg_grid(BQ, NSEG);
    k_crf_seg<<<seg_grid, 32>>>(trans);
    k_crf_fin<<<BQ, 32>>>(tags, start, endv, trans);
    k_reduce<<<1, 128>>>(out);
}